// round 12
// baseline (speedup 1.0000x reference)
#include <cuda_runtime.h>
#include <cuda_bf16.h>
#include <cstdint>

#define GB 16
#define NN 1024
#define DD 8
#define FIN 128
#define FF 64
#define INVID 0xFFFFu

// ---------------- scratch (static device globals; no allocation) ----------------
static __device__ float g_src[GB*NN];
static __device__ float g_dst[GB*NN];
static __device__ __align__(16) unsigned short g_uniq[GB*NN*DD];
static __device__ __align__(16) unsigned short g_bh[(size_t)GB*NN*NN];   // blend hi bf16, 32 MB
static __device__ __align__(16) unsigned short g_bl[(size_t)GB*NN*NN];   // blend lo bf16, 32 MB
static __device__ __align__(16) unsigned short g_hTh[(size_t)GB*FF*NN];  // h^T hi bf16, 2 MB
static __device__ __align__(16) unsigned short g_hTl[(size_t)GB*FF*NN];  // h^T lo bf16, 2 MB

// ---------------- helpers ----------------
__device__ __forceinline__ uint32_t smem_u32(const void* p) {
    uint32_t a;
    asm("{ .reg .u64 t; cvta.to.shared.u64 t, %1; cvt.u32.u64 %0, t; }" : "=r"(a) : "l"(p));
    return a;
}
__device__ __forceinline__ void cp16(uint32_t dst, const void* src) {
    asm volatile("cp.async.cg.shared.global [%0], [%1], 16;" :: "r"(dst), "l"(src));
}
__device__ __forceinline__ void ldm4(uint32_t* r, uint32_t addr) {
    asm volatile("ldmatrix.sync.aligned.m8n8.x4.shared.b16 {%0,%1,%2,%3}, [%4];"
                 : "=r"(r[0]), "=r"(r[1]), "=r"(r[2]), "=r"(r[3]) : "r"(addr));
}
__device__ __forceinline__ void mma16816(float* c, const uint32_t* a,
                                         uint32_t b0, uint32_t b1) {
    asm volatile(
        "mma.sync.aligned.m16n8k16.row.col.f32.bf16.bf16.f32 "
        "{%0,%1,%2,%3}, {%4,%5,%6,%7}, {%8,%9}, {%0,%1,%2,%3};"
        : "+f"(c[0]), "+f"(c[1]), "+f"(c[2]), "+f"(c[3])
        : "r"(a[0]), "r"(a[1]), "r"(a[2]), "r"(a[3]), "r"(b0), "r"(b1));
}
__device__ __forceinline__ void bf16_split(float v, unsigned short& hi, unsigned short& lo) {
    __nv_bfloat16 h = __float2bfloat16(v);
    hi = __bfloat16_as_ushort(h);
    lo = __bfloat16_as_ushort(__float2bfloat16(v - __bfloat162float(h)));
}
#define SWZ(o) ((o) ^ (((o) >> 3) & 0x70))

// ---------------- K1: unique neighbor lists with 0xFFFF sentinels ----------------
__global__ __launch_bounds__(256) void k_uniq(const int* __restrict__ edges) {
    const int row = blockIdx.x * 256 + threadIdx.x;
    if (row >= GB * NN) return;
    const bool is64 = (edges[1] == 0) && (edges[3] == 0) && (edges[5] == 0) && (edges[7] == 0);
    unsigned e[DD];
    #pragma unroll
    for (int d = 0; d < DD; d++) {
        int w = is64 ? edges[((size_t)row * DD + d) * 2] : edges[row * DD + d];
        e[d] = (unsigned)w & (NN - 1);
    }
    unsigned u[DD];
    int c = 0;
    #pragma unroll
    for (int d = 0; d < DD; d++) {
        bool dup = false;
        #pragma unroll
        for (int t2 = 0; t2 < DD; t2++) if (t2 < c && u[t2] == e[d]) dup = true;
        if (!dup) u[c++] = e[d];
    }
    #pragma unroll
    for (int d = 0; d < DD; d++) if (d >= c) u[d] = INVID;
    uint4 pk;
    pk.x = u[0] | (u[1] << 16);
    pk.y = u[2] | (u[3] << 16);
    pk.z = u[4] | (u[5] << 16);
    pk.w = u[6] | (u[7] << 16);
    ((uint4*)g_uniq)[row] = pk;
}

// ---------------- K2: h = atoms @ W ; emit h^T (bf16 hi/lo) + src/dst ----------------
__global__ __launch_bounds__(256) void k_h(const float* __restrict__ atoms,
                                           const float* __restrict__ W,
                                           const float* __restrict__ a) {
    const int g = blockIdx.y, i0 = blockIdx.x * 64;
    __shared__ float sAT[64][68];
    __shared__ float sW[64][64];
    __shared__ float ssrc[64], sdst[64];
    const int tid = threadIdx.x, tx = tid & 15, ty = tid >> 4;
    float acc[4][4];
    #pragma unroll
    for (int r = 0; r < 4; r++)
        #pragma unroll
        for (int c = 0; c < 4; c++) acc[r][c] = 0.f;

    const float* Ab = atoms + ((size_t)(g * NN + i0)) * FIN;
    for (int ks = 0; ks < 2; ks++) {
        #pragma unroll
        for (int p = 0; p < 4; p++) {
            const int idx = p * 256 + tid;
            const int r = idx >> 4, q = idx & 15;
            const float4 va = *(const float4*)(Ab + (size_t)r * FIN + ks * 64 + q * 4);
            sAT[q * 4 + 0][r] = va.x; sAT[q * 4 + 1][r] = va.y;
            sAT[q * 4 + 2][r] = va.z; sAT[q * 4 + 3][r] = va.w;
        }
        #pragma unroll
        for (int p = 0; p < 4; p++) {
            const int idx = p * 256 + tid;
            const int k = idx >> 4, c = (idx & 15) * 4;
            *(float4*)&sW[k][c] = *(const float4*)(W + (size_t)(ks * 64 + k) * FF + c);
        }
        __syncthreads();
        #pragma unroll 8
        for (int k = 0; k < 64; k++) {
            const float4 a4 = *(const float4*)&sAT[k][ty * 4];
            const float4 b4 = *(const float4*)&sW[k][tx * 4];
            const float av[4] = {a4.x, a4.y, a4.z, a4.w};
            const float bv[4] = {b4.x, b4.y, b4.z, b4.w};
            #pragma unroll
            for (int r = 0; r < 4; r++)
                #pragma unroll
                for (int c = 0; c < 4; c++) acc[r][c] += av[r] * bv[c];
        }
        __syncthreads();
    }
    // stage transposed h into sAT: sAT[col][row]
    #pragma unroll
    for (int r = 0; r < 4; r++)
        #pragma unroll
        for (int c = 0; c < 4; c++) sAT[tx * 4 + c][ty * 4 + r] = acc[r][c];
    float a1v[4], a2v[4];
    #pragma unroll
    for (int j = 0; j < 4; j++) { a1v[j] = a[tx * 4 + j]; a2v[j] = a[FF + tx * 4 + j]; }
    #pragma unroll
    for (int r = 0; r < 4; r++) {
        float sr = acc[r][0] * a1v[0] + acc[r][1] * a1v[1] + acc[r][2] * a1v[2] + acc[r][3] * a1v[3];
        float sd = acc[r][0] * a2v[0] + acc[r][1] * a2v[1] + acc[r][2] * a2v[2] + acc[r][3] * a2v[3];
        #pragma unroll
        for (int off = 8; off > 0; off >>= 1) {
            sr += __shfl_xor_sync(0xFFFFFFFFu, sr, off);
            sd += __shfl_xor_sync(0xFFFFFFFFu, sd, off);
        }
        if (tx == 0) { ssrc[ty * 4 + r] = sr; sdst[ty * 4 + r] = sd; }
    }
    __syncthreads();
    {
        const int cc = tid >> 2, rb = (tid & 3) * 16;
        unsigned int hw[8], lw[8];
        #pragma unroll
        for (int j = 0; j < 8; j++) {
            unsigned short h0, l0, h1, l1;
            bf16_split(sAT[cc][rb + 2 * j], h0, l0);
            bf16_split(sAT[cc][rb + 2 * j + 1], h1, l1);
            hw[j] = (unsigned)h0 | ((unsigned)h1 << 16);
            lw[j] = (unsigned)l0 | ((unsigned)l1 << 16);
        }
        const size_t base = (size_t)g * FF * NN + (size_t)cc * NN + i0 + rb;
        uint4* dh = (uint4*)(g_hTh + base);
        uint4* dl = (uint4*)(g_hTl + base);
        dh[0] = make_uint4(hw[0], hw[1], hw[2], hw[3]);
        dh[1] = make_uint4(hw[4], hw[5], hw[6], hw[7]);
        dl[0] = make_uint4(lw[0], lw[1], lw[2], lw[3]);
        dl[1] = make_uint4(lw[4], lw[5], lw[6], lw[7]);
    }
    if (tid < 64) {
        g_src[g * NN + i0 + tid] = ssrc[tid];
        g_dst[g * NN + i0 + tid] = sdst[tid];
    }
}

// ---------------- K3: blended rows, warp-per-row; emit bf16 hi/lo ----------------
__global__ __launch_bounds__(256) void k_blend(void) {
    const int g = blockIdx.y, rbase = blockIdx.x * 32;
    __shared__ __align__(16) unsigned short tbl[NN * DD];
    __shared__ __align__(16) float accs[8][NN];
    const int t = threadIdx.x, w = t >> 5, lane = t & 31;

    {
        const uint4* s4 = (const uint4*)(g_uniq + (size_t)g * NN * DD);
        uint4* d4 = (uint4*)tbl;
        #pragma unroll
        for (int p = 0; p < 4; p++) d4[p * 256 + t] = s4[p * 256 + t];
    }
    __syncthreads();

    float* A = accs[w];
    float4* A4 = (float4*)A;

    for (int rr = 0; rr < 4; rr++) {
        const int i = rbase + rr * 8 + w;
        #pragma unroll
        for (int q = 0; q < 8; q++) A4[q * 32 + lane] = make_float4(0.f, 0.f, 0.f, 0.f);
        __syncwarp();
        const unsigned short* ti = &tbl[i * DD];
        if (lane < 8) {
            const unsigned j = ti[lane];
            if (j != INVID) atomicAdd(&A[j], 1.0f);
        }
        #pragma unroll
        for (int q = 0; q < 2; q++) {
            const int p = q * 32 + lane;
            const unsigned k1 = ti[p >> 3];
            if (k1 != INVID) {
                const unsigned j = tbl[k1 * DD + (p & 7)];
                if (j != INVID) atomicAdd(&A[j], 1.0f);
            }
        }
        #pragma unroll
        for (int q = 0; q < 16; q++) {
            const int p = q * 32 + lane;
            const unsigned k1 = ti[p >> 6];
            if (k1 == INVID) continue;
            const unsigned m = tbl[k1 * DD + ((p >> 3) & 7)];
            if (m == INVID) continue;
            const unsigned j = tbl[m * DD + (p & 7)];
            if (j != INVID) atomicAdd(&A[j], 1.0f);
        }
        __syncwarp();
        float4 v[8];
        float mm = 0.f;
        #pragma unroll
        for (int q = 0; q < 8; q++) {
            v[q] = A4[q * 32 + lane];
            mm = fmaxf(mm, fmaxf(fmaxf(v[q].x, v[q].y), fmaxf(v[q].z, v[q].w)));
        }
        #pragma unroll
        for (int off = 16; off > 0; off >>= 1) mm = fmaxf(mm, __shfl_xor_sync(0xFFFFFFFFu, mm, off));
        float ss = 0.f;
        #pragma unroll
        for (int q = 0; q < 8; q++) {
            v[q].x = __expf(v[q].x - mm); v[q].y = __expf(v[q].y - mm);
            v[q].z = __expf(v[q].z - mm); v[q].w = __expf(v[q].w - mm);
            ss += (v[q].x + v[q].y) + (v[q].z + v[q].w);
            A4[q * 32 + lane] = v[q];
        }
        #pragma unroll
        for (int off = 16; off > 0; off >>= 1) ss += __shfl_xor_sync(0xFFFFFFFFu, ss, off);
        const float Z = ss;
        __syncwarp();
        {
            const unsigned j = (lane < 8) ? (unsigned)ti[lane] : INVID;
            const bool valid = (j != INVID);
            float x = -3.0e38f;
            if (valid) {
                const float vv = g_src[g * NN + i] + g_dst[g * NN + j];
                x = (vv > 0.f) ? vv : 0.2f * vv;
            }
            float me = x;
            #pragma unroll
            for (int off = 4; off > 0; off >>= 1) me = fmaxf(me, __shfl_xor_sync(0xFFFFFFFFu, me, off));
            const float ev = valid ? __expf(x - me) : 0.f;
            float Za = ev;
            #pragma unroll
            for (int off = 4; off > 0; off >>= 1) Za += __shfl_xor_sync(0xFFFFFFFFu, Za, off);
            if (valid) atomicAdd(&A[j], (ev / Za) * Z);
        }
        __syncwarp();
        const float sc = 0.5f / Z;
        uint2* oh = (uint2*)(g_bh + ((size_t)(g * NN + i)) * NN);
        uint2* ol = (uint2*)(g_bl + ((size_t)(g * NN + i)) * NN);
        #pragma unroll
        for (int q = 0; q < 8; q++) {
            float4 o = A4[q * 32 + lane];
            o.x *= sc; o.y *= sc; o.z *= sc; o.w *= sc;
            unsigned short h0, l0, h1, l1, h2, l2, h3, l3;
            bf16_split(o.x, h0, l0); bf16_split(o.y, h1, l1);
            bf16_split(o.z, h2, l2); bf16_split(o.w, h3, l3);
            uint2 ph, pl;
            ph.x = (unsigned)h0 | ((unsigned)h1 << 16);
            ph.y = (unsigned)h2 | ((unsigned)h3 << 16);
            pl.x = (unsigned)l0 | ((unsigned)l1 << 16);
            pl.y = (unsigned)l2 | ((unsigned)l3 << 16);
            oh[q * 32 + lane] = ph;
            ol[q * 32 + lane] = pl;
        }
        __syncwarp();
    }
}

// ---------------- K4: out = elu(blend @ h) via mma.sync bf16, 2-term split ----------------
// M=128/N=64 tile per CTA, K chunks of 64, cp.async 4-stage pipeline.
// smem per stage: Ah 16K | Al 16K | Bh 8K | Bl 8K = 48K; 4 stages = 192K.
#define AOFF_L 16384
#define BOFF   32768
#define BOFF_L 40960
#define BUFS   49152
#define NSTAGE 4
#define NCHUNK 16
#define GEMM_SMEM (NSTAGE * BUFS)

__device__ __forceinline__ void load_chunk(uint32_t bs, int c, size_t arow, size_t brow, int tid) {
    #pragma unroll
    for (int p = 0; p < 4; p++) {
        const int idx = p * 256 + tid;
        const int r = idx >> 3, seg = idx & 7;
        const uint32_t d = bs + SWZ(r * 128 + seg * 16);
        const size_t off = arow + (size_t)r * NN + c * 64 + seg * 8;
        cp16(d, g_bh + off);
        cp16(d + AOFF_L, g_bl + off);
    }
    #pragma unroll
    for (int p = 0; p < 2; p++) {
        const int idx = p * 256 + tid;
        const int r = idx >> 3, seg = idx & 7;
        const uint32_t d = bs + BOFF + SWZ(r * 128 + seg * 16);
        const size_t off = brow + (size_t)r * NN + c * 64 + seg * 8;
        cp16(d, g_hTh + off);
        cp16(d + (BOFF_L - BOFF), g_hTl + off);
    }
    asm volatile("cp.async.commit_group;" ::: "memory");
}

__global__ __launch_bounds__(256) void k_gemm(float* __restrict__ out) {
    extern __shared__ __align__(1024) char smem[];
    const uint32_t sb = smem_u32(smem);
    const int tid = threadIdx.x, lane = tid & 31, wid = tid >> 5;
    const int wm = wid >> 1, wn = wid & 1;
    const int g = blockIdx.y, i0 = blockIdx.x * 128;

    const size_t arow = (size_t)(g * NN + i0) * NN;
    const size_t brow = (size_t)g * FF * NN;

    float acc[2][4][4];
    #pragma unroll
    for (int mt = 0; mt < 2; mt++)
        #pragma unroll
        for (int nt = 0; nt < 4; nt++)
            #pragma unroll
            for (int q = 0; q < 4; q++) acc[mt][nt][q] = 0.f;

    // per-thread ldmatrix row bases
    const int arow_l = wm * 32 + (lane & 15);          // + mt*16
    const int brow_l = wn * 32 + (lane & 7) + ((lane >> 4) & 1) * 8;  // + nt2*16
    const uint32_t akh = (lane >> 4) * 16;             // k-half byte offset for A
    const uint32_t bkh = ((lane >> 3) & 1) * 16;       // k-half byte offset for B

    // prologue: 3 chunks in flight
    load_chunk(sb + 0 * BUFS, 0, arow, brow, tid);
    load_chunk(sb + 1 * BUFS, 1, arow, brow, tid);
    load_chunk(sb + 2 * BUFS, 2, arow, brow, tid);

    for (int c = 0; c < NCHUNK; c++) {
        // wait for chunk c (allow the 2 younger groups to stay in flight)
        asm volatile("cp.async.wait_group 2;" ::: "memory");
        __syncthreads();   // everyone done computing chunk c-1; buf (c+3)%4 free
        if (c + 3 < NCHUNK)
            load_chunk(sb + ((c + 3) & (NSTAGE - 1)) * BUFS, c + 3, arow, brow, tid);
        const uint32_t bs = sb + (c & (NSTAGE - 1)) * BUFS;
        #pragma unroll
        for (int ks = 0; ks < 4; ks++) {
            const uint32_t kb = ks * 32;  // 16 elems = 32 bytes
            uint32_t ah[2][4], al[2][4];
            #pragma unroll
            for (int mt = 0; mt < 2; mt++) {
                const unsigned r = (unsigned)(arow_l + mt * 16);
                const uint32_t addr = bs + r * 128 + ((kb + akh) ^ ((r & 7) << 4));
                ldm4(ah[mt], addr);
                ldm4(al[mt], addr + AOFF_L);
            }
            uint32_t bh[2][4], bl[2][4];
            #pragma unroll
            for (int nt2 = 0; nt2 < 2; nt2++) {
                const unsigned r = (unsigned)(brow_l + nt2 * 16);
                const uint32_t addr = bs + BOFF + r * 128 + ((kb + bkh) ^ ((r & 7) << 4));
                ldm4(bh[nt2], addr);
                ldm4(bl[nt2], addr + (BOFF_L - BOFF));
            }
            #pragma unroll
            for (int mt = 0; mt < 2; mt++)
                #pragma unroll
                for (int nt = 0; nt < 4; nt++) {
                    const int nt2 = nt >> 1, s = (nt & 1) * 2;
                    mma16816(acc[mt][nt], ah[mt], bh[nt2][s], bh[nt2][s + 1]);
                    mma16816(acc[mt][nt], ah[mt], bl[nt2][s], bl[nt2][s + 1]);
                    mma16816(acc[mt][nt], al[mt], bh[nt2][s], bh[nt2][s + 1]);
                }
        }
    }

    // epilogue: ELU + store
    const int g4 = lane >> 2, tig = lane & 3;
    #pragma unroll
    for (int mt = 0; mt < 2; mt++)
        #pragma unroll
        for (int nt = 0; nt < 4; nt++) {
            const int col = wn * 32 + nt * 8 + tig * 2;
            const int r0 = i0 + wm * 32 + mt * 16 + g4;
            float2 v0, v1;
            v0.x = acc[mt][nt][0]; v0.y = acc[mt][nt][1];
            v1.x = acc[mt][nt][2]; v1.y = acc[mt][nt][3];
            v0.x = (v0.x > 0.f) ? v0.x : (expf(v0.x) - 1.f);
            v0.y = (v0.y > 0.f) ? v0.y : (expf(v0.y) - 1.f);
            v1.x = (v1.x > 0.f) ? v1.x : (expf(v1.x) - 1.f);
            v1.y = (v1.y > 0.f) ? v1.y : (expf(v1.y) - 1.f);
            *(float2*)(out + ((size_t)(g * NN + r0)) * FF + col) = v0;
            *(float2*)(out + ((size_t)(g * NN + r0 + 8)) * FF + col) = v1;
        }
}

// ---------------- launcher ----------------
extern "C" void kernel_launch(void* const* d_in, const int* in_sizes, int n_in,
                              void* d_out, int out_size) {
    const float* atoms = (const float*)d_in[0];
    const int*   edges = (const int*)d_in[1];
    const float* W     = (const float*)d_in[2];
    const float* a     = (const float*)d_in[3];
    float* out = (float*)d_out;
    (void)in_sizes; (void)n_in; (void)out_size;

    cudaFuncSetAttribute(k_gemm, cudaFuncAttributeMaxDynamicSharedMemorySize, GEMM_SMEM);
    k_h<<<dim3(16, GB), 256>>>(atoms, W, a);
    k_uniq<<<(GB * NN) / 256, 256>>>(edges);
    k_blend<<<dim3(32, GB), 256>>>();
    k_gemm<<<dim3(8, GB), 256, GEMM_SMEM>>>(out);
}

// round 13
// speedup vs baseline: 1.5261x; 1.5261x over previous
#include <cuda_runtime.h>
#include <cuda_bf16.h>
#include <cstdint>

#define GB 16
#define NN 1024
#define DD 8
#define FIN 128
#define FF 64
#define INVID 0xFFFFu

// ---------------- scratch (static device globals; no allocation) ----------------
static __device__ float g_src[GB*NN];
static __device__ float g_dst[GB*NN];
static __device__ __align__(16) unsigned short g_uniq[GB*NN*DD];
static __device__ __align__(16) unsigned short g_bh[(size_t)GB*NN*NN];   // blend hi bf16, 32 MB
static __device__ __align__(16) unsigned short g_bl[(size_t)GB*NN*NN];   // blend lo bf16, 32 MB
static __device__ __align__(16) unsigned short g_hTh[(size_t)GB*FF*NN];  // h^T hi bf16, 2 MB
static __device__ __align__(16) unsigned short g_hTl[(size_t)GB*FF*NN];  // h^T lo bf16, 2 MB

// ---------------- helpers ----------------
__device__ __forceinline__ uint32_t smem_u32(const void* p) {
    uint32_t a;
    asm("{ .reg .u64 t; cvta.to.shared.u64 t, %1; cvt.u32.u64 %0, t; }" : "=r"(a) : "l"(p));
    return a;
}
__device__ __forceinline__ void cp16(uint32_t dst, const void* src) {
    asm volatile("cp.async.cg.shared.global [%0], [%1], 16;" :: "r"(dst), "l"(src));
}
__device__ __forceinline__ void ldm4(uint32_t* r, uint32_t addr) {
    asm volatile("ldmatrix.sync.aligned.m8n8.x4.shared.b16 {%0,%1,%2,%3}, [%4];"
                 : "=r"(r[0]), "=r"(r[1]), "=r"(r[2]), "=r"(r[3]) : "r"(addr));
}
__device__ __forceinline__ void mma16816(float* c, const uint32_t* a,
                                         uint32_t b0, uint32_t b1) {
    asm volatile(
        "mma.sync.aligned.m16n8k16.row.col.f32.bf16.bf16.f32 "
        "{%0,%1,%2,%3}, {%4,%5,%6,%7}, {%8,%9}, {%0,%1,%2,%3};"
        : "+f"(c[0]), "+f"(c[1]), "+f"(c[2]), "+f"(c[3])
        : "r"(a[0]), "r"(a[1]), "r"(a[2]), "r"(a[3]), "r"(b0), "r"(b1));
}
__device__ __forceinline__ void bf16_split(float v, unsigned short& hi, unsigned short& lo) {
    __nv_bfloat16 h = __float2bfloat16(v);
    hi = __bfloat16_as_ushort(h);
    lo = __bfloat16_as_ushort(__float2bfloat16(v - __bfloat162float(h)));
}
#define SWZ(o) ((o) ^ (((o) >> 3) & 0x70))

// ---------------- K1: unique neighbor lists with 0xFFFF sentinels ----------------
__global__ __launch_bounds__(256) void k_uniq(const int* __restrict__ edges) {
    const int row = blockIdx.x * 256 + threadIdx.x;
    if (row >= GB * NN) return;
    const bool is64 = (edges[1] == 0) && (edges[3] == 0) && (edges[5] == 0) && (edges[7] == 0);
    unsigned e[DD];
    #pragma unroll
    for (int d = 0; d < DD; d++) {
        int w = is64 ? edges[((size_t)row * DD + d) * 2] : edges[row * DD + d];
        e[d] = (unsigned)w & (NN - 1);
    }
    unsigned u[DD];
    int c = 0;
    #pragma unroll
    for (int d = 0; d < DD; d++) {
        bool dup = false;
        #pragma unroll
        for (int t2 = 0; t2 < DD; t2++) if (t2 < c && u[t2] == e[d]) dup = true;
        if (!dup) u[c++] = e[d];
    }
    #pragma unroll
    for (int d = 0; d < DD; d++) if (d >= c) u[d] = INVID;
    uint4 pk;
    pk.x = u[0] | (u[1] << 16);
    pk.y = u[2] | (u[3] << 16);
    pk.z = u[4] | (u[5] << 16);
    pk.w = u[6] | (u[7] << 16);
    ((uint4*)g_uniq)[row] = pk;
}

// ---------------- K2: h = atoms @ W ; emit h^T (bf16 hi/lo) + src/dst ----------------
__global__ __launch_bounds__(256) void k_h(const float* __restrict__ atoms,
                                           const float* __restrict__ W,
                                           const float* __restrict__ a) {
    const int g = blockIdx.y, i0 = blockIdx.x * 64;
    __shared__ float sAT[64][68];
    __shared__ float sW[64][64];
    __shared__ float ssrc[64], sdst[64];
    const int tid = threadIdx.x, tx = tid & 15, ty = tid >> 4;
    float acc[4][4];
    #pragma unroll
    for (int r = 0; r < 4; r++)
        #pragma unroll
        for (int c = 0; c < 4; c++) acc[r][c] = 0.f;

    const float* Ab = atoms + ((size_t)(g * NN + i0)) * FIN;
    for (int ks = 0; ks < 2; ks++) {
        #pragma unroll
        for (int p = 0; p < 4; p++) {
            const int idx = p * 256 + tid;
            const int r = idx >> 4, q = idx & 15;
            const float4 va = *(const float4*)(Ab + (size_t)r * FIN + ks * 64 + q * 4);
            sAT[q * 4 + 0][r] = va.x; sAT[q * 4 + 1][r] = va.y;
            sAT[q * 4 + 2][r] = va.z; sAT[q * 4 + 3][r] = va.w;
        }
        #pragma unroll
        for (int p = 0; p < 4; p++) {
            const int idx = p * 256 + tid;
            const int k = idx >> 4, c = (idx & 15) * 4;
            *(float4*)&sW[k][c] = *(const float4*)(W + (size_t)(ks * 64 + k) * FF + c);
        }
        __syncthreads();
        #pragma unroll 8
        for (int k = 0; k < 64; k++) {
            const float4 a4 = *(const float4*)&sAT[k][ty * 4];
            const float4 b4 = *(const float4*)&sW[k][tx * 4];
            const float av[4] = {a4.x, a4.y, a4.z, a4.w};
            const float bv[4] = {b4.x, b4.y, b4.z, b4.w};
            #pragma unroll
            for (int r = 0; r < 4; r++)
                #pragma unroll
                for (int c = 0; c < 4; c++) acc[r][c] += av[r] * bv[c];
        }
        __syncthreads();
    }
    // stage transposed h into sAT: sAT[col][row]
    #pragma unroll
    for (int r = 0; r < 4; r++)
        #pragma unroll
        for (int c = 0; c < 4; c++) sAT[tx * 4 + c][ty * 4 + r] = acc[r][c];
    float a1v[4], a2v[4];
    #pragma unroll
    for (int j = 0; j < 4; j++) { a1v[j] = a[tx * 4 + j]; a2v[j] = a[FF + tx * 4 + j]; }
    #pragma unroll
    for (int r = 0; r < 4; r++) {
        float sr = acc[r][0] * a1v[0] + acc[r][1] * a1v[1] + acc[r][2] * a1v[2] + acc[r][3] * a1v[3];
        float sd = acc[r][0] * a2v[0] + acc[r][1] * a2v[1] + acc[r][2] * a2v[2] + acc[r][3] * a2v[3];
        #pragma unroll
        for (int off = 8; off > 0; off >>= 1) {
            sr += __shfl_xor_sync(0xFFFFFFFFu, sr, off);
            sd += __shfl_xor_sync(0xFFFFFFFFu, sd, off);
        }
        if (tx == 0) { ssrc[ty * 4 + r] = sr; sdst[ty * 4 + r] = sd; }
    }
    __syncthreads();
    {
        const int cc = tid >> 2, rb = (tid & 3) * 16;
        unsigned int hw[8], lw[8];
        #pragma unroll
        for (int j = 0; j < 8; j++) {
            unsigned short h0, l0, h1, l1;
            bf16_split(sAT[cc][rb + 2 * j], h0, l0);
            bf16_split(sAT[cc][rb + 2 * j + 1], h1, l1);
            hw[j] = (unsigned)h0 | ((unsigned)h1 << 16);
            lw[j] = (unsigned)l0 | ((unsigned)l1 << 16);
        }
        const size_t base = (size_t)g * FF * NN + (size_t)cc * NN + i0 + rb;
        uint4* dh = (uint4*)(g_hTh + base);
        uint4* dl = (uint4*)(g_hTl + base);
        dh[0] = make_uint4(hw[0], hw[1], hw[2], hw[3]);
        dh[1] = make_uint4(hw[4], hw[5], hw[6], hw[7]);
        dl[0] = make_uint4(lw[0], lw[1], lw[2], lw[3]);
        dl[1] = make_uint4(lw[4], lw[5], lw[6], lw[7]);
    }
    if (tid < 64) {
        g_src[g * NN + i0 + tid] = ssrc[tid];
        g_dst[g * NN + i0 + tid] = sdst[tid];
    }
}

// ---------------- K3: blended rows, warp-per-row, register-resident epilogue ----------------
__global__ __launch_bounds__(256) void k_blend(void) {
    const int g = blockIdx.y, rbase = blockIdx.x * 32;
    __shared__ __align__(16) unsigned short tbl[NN * DD];
    __shared__ __align__(16) float accs[8][NN];
    const int t = threadIdx.x, w = t >> 5, lane = t & 31;

    {
        const uint4* s4 = (const uint4*)(g_uniq + (size_t)g * NN * DD);
        uint4* d4 = (uint4*)tbl;
        #pragma unroll
        for (int p = 0; p < 4; p++) d4[p * 256 + t] = s4[p * 256 + t];
    }
    float* A = accs[w];
    float4* A4 = (float4*)A;
    // zero own accumulator once; thereafter re-zeroed during the read pass
    #pragma unroll
    for (int q = 0; q < 8; q++) A4[q * 32 + lane] = make_float4(0.f, 0.f, 0.f, 0.f);
    __syncthreads();

    for (int rr = 0; rr < 4; rr++) {
        const int i = rbase + rr * 8 + w;
        const unsigned short* ti = &tbl[i * DD];
        // ---- scatter integer counts for A, A^2, A^3 (exact in fp32 -> deterministic)
        if (lane < 8) {
            const unsigned j = ti[lane];
            if (j != INVID) atomicAdd(&A[j], 1.0f);
        }
        #pragma unroll
        for (int q = 0; q < 2; q++) {
            const int p = q * 32 + lane;
            const unsigned k1 = ti[p >> 3];
            if (k1 != INVID) {
                const unsigned j = tbl[k1 * DD + (p & 7)];
                if (j != INVID) atomicAdd(&A[j], 1.0f);
            }
        }
        #pragma unroll
        for (int q = 0; q < 16; q++) {
            const int p = q * 32 + lane;
            const unsigned k1 = ti[p >> 6];
            if (k1 == INVID) continue;
            const unsigned m = tbl[k1 * DD + ((p >> 3) & 7)];
            if (m == INVID) continue;
            const unsigned j = tbl[m * DD + (p & 7)];
            if (j != INVID) atomicAdd(&A[j], 1.0f);
        }
        // ---- attention over unique neighbors (independent of counts)
        unsigned aj = INVID;
        float aw = 0.f;
        {
            aj = (lane < 8) ? (unsigned)ti[lane] : INVID;
            const bool valid = (aj != INVID);
            float x = -3.0e38f;
            if (valid) {
                const float vv = g_src[g * NN + i] + g_dst[g * NN + aj];
                x = (vv > 0.f) ? vv : 0.2f * vv;       // leaky_relu
            }
            float me = x;
            #pragma unroll
            for (int off = 4; off > 0; off >>= 1) me = fmaxf(me, __shfl_xor_sync(0xFFFFFFFFu, me, off));
            const float ev = valid ? __expf(x - me) : 0.f;
            float Za = ev;
            #pragma unroll
            for (int off = 4; off > 0; off >>= 1) Za += __shfl_xor_sync(0xFFFFFFFFu, Za, off);
            aw = valid ? (0.5f * ev / Za) : 0.f;       // RATIO * att weight
        }
        __syncwarp();
        // ---- read counts into registers, zero for next row
        float4 v[8];
        float mm = 0.f;   // counts >= 0
        #pragma unroll
        for (int q = 0; q < 8; q++) {
            v[q] = A4[q * 32 + lane];
            A4[q * 32 + lane] = make_float4(0.f, 0.f, 0.f, 0.f);
            mm = fmaxf(mm, fmaxf(fmaxf(v[q].x, v[q].y), fmaxf(v[q].z, v[q].w)));
        }
        #pragma unroll
        for (int off = 16; off > 0; off >>= 1) mm = fmaxf(mm, __shfl_xor_sync(0xFFFFFFFFu, mm, off));
        float ss = 0.f;
        #pragma unroll
        for (int q = 0; q < 8; q++) {
            v[q].x = __expf(v[q].x - mm); v[q].y = __expf(v[q].y - mm);
            v[q].z = __expf(v[q].z - mm); v[q].w = __expf(v[q].w - mm);
            ss += (v[q].x + v[q].y) + (v[q].z + v[q].w);
        }
        #pragma unroll
        for (int off = 16; off > 0; off >>= 1) ss += __shfl_xor_sync(0xFFFFFFFFu, ss, off);
        const float sc = 0.5f / ss;                    // RATIO / Z
        // ---- scale structure part in regs
        #pragma unroll
        for (int q = 0; q < 8; q++) {
            v[q].x *= sc; v[q].y *= sc; v[q].z *= sc; v[q].w *= sc;
        }
        // ---- fold the <=8 attention weights: broadcast (j, w), owner lane adds
        #pragma unroll
        for (int d = 0; d < 8; d++) {
            const unsigned jj = __shfl_sync(0xFFFFFFFFu, aj, d);
            const float ww = __shfl_sync(0xFFFFFFFFu, aw, d);
            if (jj == INVID) continue;
            if (lane == (int)((jj >> 2) & 31)) {
                const int q = jj >> 7, cmp = jj & 3;
                float4& vq0 = v[0];
                // static switch on q to avoid local-memory indexing
                #pragma unroll
                for (int qq = 0; qq < 8; qq++) if (qq == q) {
                    if (cmp == 0) v[qq].x += ww;
                    else if (cmp == 1) v[qq].y += ww;
                    else if (cmp == 2) v[qq].z += ww;
                    else v[qq].w += ww;
                }
                (void)vq0;
            }
        }
        // ---- split to bf16 hi/lo and store
        uint2* oh = (uint2*)(g_bh + ((size_t)(g * NN + i)) * NN);
        uint2* ol = (uint2*)(g_bl + ((size_t)(g * NN + i)) * NN);
        #pragma unroll
        for (int q = 0; q < 8; q++) {
            unsigned short h0, l0, h1, l1, h2, l2, h3, l3;
            bf16_split(v[q].x, h0, l0); bf16_split(v[q].y, h1, l1);
            bf16_split(v[q].z, h2, l2); bf16_split(v[q].w, h3, l3);
            uint2 ph, pl;
            ph.x = (unsigned)h0 | ((unsigned)h1 << 16);
            ph.y = (unsigned)h2 | ((unsigned)h3 << 16);
            pl.x = (unsigned)l0 | ((unsigned)l1 << 16);
            pl.y = (unsigned)l2 | ((unsigned)l3 << 16);
            oh[q * 32 + lane] = ph;
            ol[q * 32 + lane] = pl;
        }
        __syncwarp();
    }
}

// ---------------- K4: out = elu(blend @ h) via mma.sync bf16, 2-term split ----------------
// (R11-proven structure: 2-stage, compute -> load next -> wait_group 1)
#define AOFF_L 16384
#define BOFF   32768
#define BOFF_L 40960
#define BUFS   49152
#define GEMM_SMEM (2 * BUFS)

__device__ __forceinline__ void load_chunk(uint32_t bs, int c, size_t arow, size_t brow, int tid) {
    #pragma unroll
    for (int p = 0; p < 4; p++) {
        const int idx = p * 256 + tid;
        const int r = idx >> 3, seg = idx & 7;
        const uint32_t d = bs + SWZ(r * 128 + seg * 16);
        const size_t off = arow + (size_t)r * NN + c * 64 + seg * 8;
        cp16(d, g_bh + off);
        cp16(d + AOFF_L, g_bl + off);
    }
    #pragma unroll
    for (int p = 0; p < 2; p++) {
        const int idx = p * 256 + tid;
        const int r = idx >> 3, seg = idx & 7;
        const uint32_t d = bs + BOFF + SWZ(r * 128 + seg * 16);
        const size_t off = brow + (size_t)r * NN + c * 64 + seg * 8;
        cp16(d, g_hTh + off);
        cp16(d + (BOFF_L - BOFF), g_hTl + off);
    }
    asm volatile("cp.async.commit_group;" ::: "memory");
}

__global__ __launch_bounds__(256) void k_gemm(float* __restrict__ out) {
    extern __shared__ __align__(1024) char smem[];
    const uint32_t sb = smem_u32(smem);
    const int tid = threadIdx.x, lane = tid & 31, wid = tid >> 5;
    const int wm = wid >> 1, wn = wid & 1;
    const int g = blockIdx.y, i0 = blockIdx.x * 128;

    const size_t arow = (size_t)(g * NN + i0) * NN;
    const size_t brow = (size_t)g * FF * NN;

    float acc[2][4][4];
    #pragma unroll
    for (int mt = 0; mt < 2; mt++)
        #pragma unroll
        for (int nt = 0; nt < 4; nt++)
            #pragma unroll
            for (int q = 0; q < 4; q++) acc[mt][nt][q] = 0.f;

    const int arow_l = wm * 32 + (lane & 15);
    const int brow_l = wn * 32 + (lane & 7) + ((lane >> 4) & 1) * 8;
    const uint32_t akh = (lane >> 4) * 16;
    const uint32_t bkh = ((lane >> 3) & 1) * 16;

    // prologue: chunks 0 and 1
    load_chunk(sb, 0, arow, brow, tid);
    load_chunk(sb + BUFS, 1, arow, brow, tid);
    asm volatile("cp.async.wait_group 1;" ::: "memory");
    __syncthreads();

    for (int c = 0; c < 16; c++) {
        const uint32_t bs = sb + (c & 1) * BUFS;
        #pragma unroll
        for (int ks = 0; ks < 4; ks++) {
            const uint32_t kb = ks * 32;
            uint32_t ah[2][4], al[2][4];
            #pragma unroll
            for (int mt = 0; mt < 2; mt++) {
                const unsigned r = (unsigned)(arow_l + mt * 16);
                const uint32_t addr = bs + r * 128 + ((kb + akh) ^ ((r & 7) << 4));
                ldm4(ah[mt], addr);
                ldm4(al[mt], addr + AOFF_L);
            }
            uint32_t bh[2][4], bl[2][4];
            #pragma unroll
            for (int nt2 = 0; nt2 < 2; nt2++) {
                const unsigned r = (unsigned)(brow_l + nt2 * 16);
                const uint32_t addr = bs + BOFF + r * 128 + ((kb + bkh) ^ ((r & 7) << 4));
                ldm4(bh[nt2], addr);
                ldm4(bl[nt2], addr + (BOFF_L - BOFF));
            }
            #pragma unroll
            for (int mt = 0; mt < 2; mt++)
                #pragma unroll
                for (int nt = 0; nt < 4; nt++) {
                    const int nt2 = nt >> 1, s = (nt & 1) * 2;
                    mma16816(acc[mt][nt], ah[mt], bh[nt2][s], bh[nt2][s + 1]);
                    mma16816(acc[mt][nt], ah[mt], bl[nt2][s], bl[nt2][s + 1]);
                    mma16816(acc[mt][nt], al[mt], bh[nt2][s], bh[nt2][s + 1]);
                }
        }
        __syncthreads();
        if (c + 2 < 16) {
            load_chunk(bs, c + 2, arow, brow, tid);
            asm volatile("cp.async.wait_group 1;" ::: "memory");
        } else {
            asm volatile("cp.async.wait_group 0;" ::: "memory");
        }
        __syncthreads();
    }

    // epilogue: ELU + store
    const int g4 = lane >> 2, tig = lane & 3;
    #pragma unroll
    for (int mt = 0; mt < 2; mt++)
        #pragma unroll
        for (int nt = 0; nt < 4; nt++) {
            const int col = wn * 32 + nt * 8 + tig * 2;
            const int r0 = i0 + wm * 32 + mt * 16 + g4;
            float2 v0, v1;
            v0.x = acc[mt][nt][0]; v0.y = acc[mt][nt][1];
            v1.x = acc[mt][nt][2]; v1.y = acc[mt][nt][3];
            v0.x = (v0.x > 0.f) ? v0.x : (expf(v0.x) - 1.f);
            v0.y = (v0.y > 0.f) ? v0.y : (expf(v0.y) - 1.f);
            v1.x = (v1.x > 0.f) ? v1.x : (expf(v1.x) - 1.f);
            v1.y = (v1.y > 0.f) ? v1.y : (expf(v1.y) - 1.f);
            *(float2*)(out + ((size_t)(g * NN + r0)) * FF + col) = v0;
            *(float2*)(out + ((size_t)(g * NN + r0 + 8)) * FF + col) = v1;
        }
}

// ---------------- launcher ----------------
extern "C" void kernel_launch(void* const* d_in, const int* in_sizes, int n_in,
                              void* d_out, int out_size) {
    const float* atoms = (const float*)d_in[0];
    const int*   edges = (const int*)d_in[1];
    const float* W     = (const float*)d_in[2];
    const float* a     = (const float*)d_in[3];
    float* out = (float*)d_out;
    (void)in_sizes; (void)n_in; (void)out_size;

    cudaFuncSetAttribute(k_gemm, cudaFuncAttributeMaxDynamicSharedMemorySize, GEMM_SMEM);
    k_h<<<dim3(16, GB), 256>>>(atoms, W, a);
    k_uniq<<<(GB * NN) / 256, 256>>>(edges);
    k_blend<<<dim3(32, GB), 256>>>();
    k_gemm<<<dim3(8, GB), 256, GEMM_SMEM>>>(out);
}

// round 14
// speedup vs baseline: 1.8110x; 1.1866x over previous
#include <cuda_runtime.h>
#include <cuda_bf16.h>
#include <cstdint>

#define GB 16
#define NN 1024
#define DD 8
#define FIN 128
#define FF 64
#define INVID 0xFFFFu

// ---------------- scratch (static device globals; no allocation) ----------------
static __device__ float g_src[GB*NN];
static __device__ float g_dst[GB*NN];
static __device__ __align__(16) unsigned short g_uniq[GB*NN*DD];
static __device__ __align__(16) unsigned short g_bh[(size_t)GB*NN*NN];   // blend hi bf16, 32 MB
static __device__ __align__(16) unsigned short g_bl[(size_t)GB*NN*NN];   // blend lo bf16, 32 MB
static __device__ __align__(16) unsigned short g_hTh[(size_t)GB*FF*NN];  // h^T hi bf16, 2 MB
static __device__ __align__(16) unsigned short g_hTl[(size_t)GB*FF*NN];  // h^T lo bf16, 2 MB

// ---------------- helpers ----------------
__device__ __forceinline__ uint32_t smem_u32(const void* p) {
    uint32_t a;
    asm("{ .reg .u64 t; cvta.to.shared.u64 t, %1; cvt.u32.u64 %0, t; }" : "=r"(a) : "l"(p));
    return a;
}
__device__ __forceinline__ void cp16(uint32_t dst, const void* src) {
    asm volatile("cp.async.cg.shared.global [%0], [%1], 16;" :: "r"(dst), "l"(src));
}
__device__ __forceinline__ void ldm4(uint32_t* r, uint32_t addr) {
    asm volatile("ldmatrix.sync.aligned.m8n8.x4.shared.b16 {%0,%1,%2,%3}, [%4];"
                 : "=r"(r[0]), "=r"(r[1]), "=r"(r[2]), "=r"(r[3]) : "r"(addr));
}
__device__ __forceinline__ void mma16816(float* c, const uint32_t* a,
                                         uint32_t b0, uint32_t b1) {
    asm volatile(
        "mma.sync.aligned.m16n8k16.row.col.f32.bf16.bf16.f32 "
        "{%0,%1,%2,%3}, {%4,%5,%6,%7}, {%8,%9}, {%0,%1,%2,%3};"
        : "+f"(c[0]), "+f"(c[1]), "+f"(c[2]), "+f"(c[3])
        : "r"(a[0]), "r"(a[1]), "r"(a[2]), "r"(a[3]), "r"(b0), "r"(b1));
}
__device__ __forceinline__ void bf16_split(float v, unsigned short& hi, unsigned short& lo) {
    __nv_bfloat16 h = __float2bfloat16(v);
    hi = __bfloat16_as_ushort(h);
    lo = __bfloat16_as_ushort(__float2bfloat16(v - __bfloat162float(h)));
}
#define SWZ(o) ((o) ^ (((o) >> 3) & 0x70))

// ---------------- K1: unique neighbor lists with 0xFFFF sentinels ----------------
__global__ __launch_bounds__(256) void k_uniq(const int* __restrict__ edges) {
    const int row = blockIdx.x * 256 + threadIdx.x;
    if (row >= GB * NN) return;
    const bool is64 = (edges[1] == 0) && (edges[3] == 0) && (edges[5] == 0) && (edges[7] == 0);
    unsigned e[DD];
    #pragma unroll
    for (int d = 0; d < DD; d++) {
        int w = is64 ? edges[((size_t)row * DD + d) * 2] : edges[row * DD + d];
        e[d] = (unsigned)w & (NN - 1);
    }
    unsigned u[DD];
    int c = 0;
    #pragma unroll
    for (int d = 0; d < DD; d++) {
        bool dup = false;
        #pragma unroll
        for (int t2 = 0; t2 < DD; t2++) if (t2 < c && u[t2] == e[d]) dup = true;
        if (!dup) u[c++] = e[d];
    }
    #pragma unroll
    for (int d = 0; d < DD; d++) if (d >= c) u[d] = INVID;
    uint4 pk;
    pk.x = u[0] | (u[1] << 16);
    pk.y = u[2] | (u[3] << 16);
    pk.z = u[4] | (u[5] << 16);
    pk.w = u[6] | (u[7] << 16);
    ((uint4*)g_uniq)[row] = pk;
}

// ---------------- K2: h = atoms @ W ; emit h^T (bf16 hi/lo) + src/dst ----------------
__global__ __launch_bounds__(256) void k_h(const float* __restrict__ atoms,
                                           const float* __restrict__ W,
                                           const float* __restrict__ a) {
    const int g = blockIdx.y, i0 = blockIdx.x * 64;
    __shared__ float sAT[64][68];
    __shared__ float sW[64][64];
    __shared__ float ssrc[64], sdst[64];
    const int tid = threadIdx.x, tx = tid & 15, ty = tid >> 4;
    float acc[4][4];
    #pragma unroll
    for (int r = 0; r < 4; r++)
        #pragma unroll
        for (int c = 0; c < 4; c++) acc[r][c] = 0.f;

    const float* Ab = atoms + ((size_t)(g * NN + i0)) * FIN;
    for (int ks = 0; ks < 2; ks++) {
        #pragma unroll
        for (int p = 0; p < 4; p++) {
            const int idx = p * 256 + tid;
            const int r = idx >> 4, q = idx & 15;
            const float4 va = *(const float4*)(Ab + (size_t)r * FIN + ks * 64 + q * 4);
            sAT[q * 4 + 0][r] = va.x; sAT[q * 4 + 1][r] = va.y;
            sAT[q * 4 + 2][r] = va.z; sAT[q * 4 + 3][r] = va.w;
        }
        #pragma unroll
        for (int p = 0; p < 4; p++) {
            const int idx = p * 256 + tid;
            const int k = idx >> 4, c = (idx & 15) * 4;
            *(float4*)&sW[k][c] = *(const float4*)(W + (size_t)(ks * 64 + k) * FF + c);
        }
        __syncthreads();
        #pragma unroll 8
        for (int k = 0; k < 64; k++) {
            const float4 a4 = *(const float4*)&sAT[k][ty * 4];
            const float4 b4 = *(const float4*)&sW[k][tx * 4];
            const float av[4] = {a4.x, a4.y, a4.z, a4.w};
            const float bv[4] = {b4.x, b4.y, b4.z, b4.w};
            #pragma unroll
            for (int r = 0; r < 4; r++)
                #pragma unroll
                for (int c = 0; c < 4; c++) acc[r][c] += av[r] * bv[c];
        }
        __syncthreads();
    }
    // stage transposed h into sAT: sAT[col][row]
    #pragma unroll
    for (int r = 0; r < 4; r++)
        #pragma unroll
        for (int c = 0; c < 4; c++) sAT[tx * 4 + c][ty * 4 + r] = acc[r][c];
    float a1v[4], a2v[4];
    #pragma unroll
    for (int j = 0; j < 4; j++) { a1v[j] = a[tx * 4 + j]; a2v[j] = a[FF + tx * 4 + j]; }
    #pragma unroll
    for (int r = 0; r < 4; r++) {
        float sr = acc[r][0] * a1v[0] + acc[r][1] * a1v[1] + acc[r][2] * a1v[2] + acc[r][3] * a1v[3];
        float sd = acc[r][0] * a2v[0] + acc[r][1] * a2v[1] + acc[r][2] * a2v[2] + acc[r][3] * a2v[3];
        #pragma unroll
        for (int off = 8; off > 0; off >>= 1) {
            sr += __shfl_xor_sync(0xFFFFFFFFu, sr, off);
            sd += __shfl_xor_sync(0xFFFFFFFFu, sd, off);
        }
        if (tx == 0) { ssrc[ty * 4 + r] = sr; sdst[ty * 4 + r] = sd; }
    }
    __syncthreads();
    {
        const int cc = tid >> 2, rb = (tid & 3) * 16;
        unsigned int hw[8], lw[8];
        #pragma unroll
        for (int j = 0; j < 8; j++) {
            unsigned short h0, l0, h1, l1;
            bf16_split(sAT[cc][rb + 2 * j], h0, l0);
            bf16_split(sAT[cc][rb + 2 * j + 1], h1, l1);
            hw[j] = (unsigned)h0 | ((unsigned)h1 << 16);
            lw[j] = (unsigned)l0 | ((unsigned)l1 << 16);
        }
        const size_t base = (size_t)g * FF * NN + (size_t)cc * NN + i0 + rb;
        uint4* dh = (uint4*)(g_hTh + base);
        uint4* dl = (uint4*)(g_hTl + base);
        dh[0] = make_uint4(hw[0], hw[1], hw[2], hw[3]);
        dh[1] = make_uint4(hw[4], hw[5], hw[6], hw[7]);
        dl[0] = make_uint4(lw[0], lw[1], lw[2], lw[3]);
        dl[1] = make_uint4(lw[4], lw[5], lw[6], lw[7]);
    }
    if (tid < 64) {
        g_src[g * NN + i0 + tid] = ssrc[tid];
        g_dst[g * NN + i0 + tid] = sdst[tid];
    }
}

// ---------------- K3: blended rows, warp-per-row, LUT softmax over integer counts ----
__global__ __launch_bounds__(256) void k_blend(void) {
    const int g = blockIdx.y, rbase = blockIdx.x * 32;
    __shared__ __align__(16) unsigned short tbl[NN * DD];   // 16 KB
    __shared__ __align__(16) unsigned int accs[8][NN];      // 32 KB (uint counts)
    __shared__ float etab[128];                             // exp LUT
    const int t = threadIdx.x, w = t >> 5, lane = t & 31;

    if (t < 128) etab[t] = expf((float)t);
    {
        const uint4* s4 = (const uint4*)(g_uniq + (size_t)g * NN * DD);
        uint4* d4 = (uint4*)tbl;
        #pragma unroll
        for (int p = 0; p < 4; p++) d4[p * 256 + t] = s4[p * 256 + t];
    }
    unsigned int* A = accs[w];
    uint4* A4 = (uint4*)A;
    #pragma unroll
    for (int q = 0; q < 8; q++) A4[q * 32 + lane] = make_uint4(0u, 0u, 0u, 0u);
    __syncthreads();

    for (int rr = 0; rr < 4; rr++) {
        const int i = rbase + rr * 8 + w;
        const unsigned short* ti = &tbl[i * DD];
        // ---- A: direct neighbors
        if (lane < 8) {
            const unsigned j = ti[lane];
            if (j != INVID) atomicAdd(&A[j], 1u);
        }
        // ---- A^2 + A^3 fused: each lane owns 2 (d,e) pairs; loads third-hop
        //      row as one LDS.128 and extracts 8 shorts.
        #pragma unroll
        for (int q = 0; q < 2; q++) {
            const int idx = q * 32 + lane;              // (d,e) in 0..63
            const unsigned k1 = ti[idx >> 3];
            if (k1 != INVID) {
                const unsigned m = tbl[k1 * DD + (idx & 7)];
                if (m != INVID) {
                    atomicAdd(&A[m], 1u);               // A^2 path count
                    const uint4 jr = *(const uint4*)&tbl[m * DD];
                    unsigned jj;
                    jj = jr.x & 0xFFFFu; if (jj != INVID) atomicAdd(&A[jj], 1u);
                    jj = jr.x >> 16;     if (jj != INVID) atomicAdd(&A[jj], 1u);
                    jj = jr.y & 0xFFFFu; if (jj != INVID) atomicAdd(&A[jj], 1u);
                    jj = jr.y >> 16;     if (jj != INVID) atomicAdd(&A[jj], 1u);
                    jj = jr.z & 0xFFFFu; if (jj != INVID) atomicAdd(&A[jj], 1u);
                    jj = jr.z >> 16;     if (jj != INVID) atomicAdd(&A[jj], 1u);
                    jj = jr.w & 0xFFFFu; if (jj != INVID) atomicAdd(&A[jj], 1u);
                    jj = jr.w >> 16;     if (jj != INVID) atomicAdd(&A[jj], 1u);
                }
            }
        }
        // ---- attention over unique neighbors (independent of counts)
        unsigned aj = INVID;
        float aw = 0.f;
        {
            aj = (lane < 8) ? (unsigned)ti[lane] : INVID;
            const bool valid = (aj != INVID);
            float x = -3.0e38f;
            if (valid) {
                const float vv = g_src[g * NN + i] + g_dst[g * NN + aj];
                x = (vv > 0.f) ? vv : 0.2f * vv;        // leaky_relu
            }
            float me = x;
            #pragma unroll
            for (int off = 4; off > 0; off >>= 1) me = fmaxf(me, __shfl_xor_sync(0xFFFFFFFFu, me, off));
            const float ev = valid ? __expf(x - me) : 0.f;
            float Za = ev;
            #pragma unroll
            for (int off = 4; off > 0; off >>= 1) Za += __shfl_xor_sync(0xFFFFFFFFu, Za, off);
            aw = valid ? (0.5f * ev / Za) : 0.f;        // RATIO * att weight
        }
        __syncwarp();
        // ---- read counts into registers, zero for next row
        uint4 u[8];
        unsigned im = 0u;
        #pragma unroll
        for (int q = 0; q < 8; q++) {
            u[q] = A4[q * 32 + lane];
            A4[q * 32 + lane] = make_uint4(0u, 0u, 0u, 0u);
            im = max(im, max(max(u[q].x, u[q].y), max(u[q].z, u[q].w)));
        }
        im = __reduce_max_sync(0xFFFFFFFFu, im);
        // ---- softmax: LUT path (max cancels in the ratio); fallback if huge counts
        float4 v[8];
        float ss = 0.f;
        if (im < 96u) {
            #pragma unroll
            for (int q = 0; q < 8; q++) {
                v[q].x = etab[u[q].x]; v[q].y = etab[u[q].y];
                v[q].z = etab[u[q].z]; v[q].w = etab[u[q].w];
                ss += (v[q].x + v[q].y) + (v[q].z + v[q].w);
            }
        } else {
            const float fm = (float)im;
            #pragma unroll
            for (int q = 0; q < 8; q++) {
                v[q].x = __expf((float)u[q].x - fm); v[q].y = __expf((float)u[q].y - fm);
                v[q].z = __expf((float)u[q].z - fm); v[q].w = __expf((float)u[q].w - fm);
                ss += (v[q].x + v[q].y) + (v[q].z + v[q].w);
            }
        }
        #pragma unroll
        for (int off = 16; off > 0; off >>= 1) ss += __shfl_xor_sync(0xFFFFFFFFu, ss, off);
        const float sc = 0.5f / ss;                     // RATIO / Z
        #pragma unroll
        for (int q = 0; q < 8; q++) {
            v[q].x *= sc; v[q].y *= sc; v[q].z *= sc; v[q].w *= sc;
        }
        // ---- fold the <=8 attention weights: broadcast (j, w), owner lane adds
        #pragma unroll
        for (int d = 0; d < 8; d++) {
            const unsigned jj = __shfl_sync(0xFFFFFFFFu, aj, d);
            const float ww = __shfl_sync(0xFFFFFFFFu, aw, d);
            if (jj == INVID) continue;
            if (lane == (int)((jj >> 2) & 31)) {
                const int q = jj >> 7, cmp = jj & 3;
                #pragma unroll
                for (int qq = 0; qq < 8; qq++) if (qq == q) {
                    if (cmp == 0) v[qq].x += ww;
                    else if (cmp == 1) v[qq].y += ww;
                    else if (cmp == 2) v[qq].z += ww;
                    else v[qq].w += ww;
                }
            }
        }
        // ---- split to bf16 hi/lo and store
        uint2* oh = (uint2*)(g_bh + ((size_t)(g * NN + i)) * NN);
        uint2* ol = (uint2*)(g_bl + ((size_t)(g * NN + i)) * NN);
        #pragma unroll
        for (int q = 0; q < 8; q++) {
            unsigned short h0, l0, h1, l1, h2, l2, h3, l3;
            bf16_split(v[q].x, h0, l0); bf16_split(v[q].y, h1, l1);
            bf16_split(v[q].z, h2, l2); bf16_split(v[q].w, h3, l3);
            uint2 ph, pl;
            ph.x = (unsigned)h0 | ((unsigned)h1 << 16);
            ph.y = (unsigned)h2 | ((unsigned)h3 << 16);
            pl.x = (unsigned)l0 | ((unsigned)l1 << 16);
            pl.y = (unsigned)l2 | ((unsigned)l3 << 16);
            oh[q * 32 + lane] = ph;
            ol[q * 32 + lane] = pl;
        }
        __syncwarp();
    }
}

// ---------------- K4: out = elu(blend @ h) via mma.sync bf16, 2-term split ----------------
// (R11-proven structure: 2-stage, compute -> load next -> wait_group 1)
#define AOFF_L 16384
#define BOFF   32768
#define BOFF_L 40960
#define BUFS   49152
#define GEMM_SMEM (2 * BUFS)

__device__ __forceinline__ void load_chunk(uint32_t bs, int c, size_t arow, size_t brow, int tid) {
    #pragma unroll
    for (int p = 0; p < 4; p++) {
        const int idx = p * 256 + tid;
        const int r = idx >> 3, seg = idx & 7;
        const uint32_t d = bs + SWZ(r * 128 + seg * 16);
        const size_t off = arow + (size_t)r * NN + c * 64 + seg * 8;
        cp16(d, g_bh + off);
        cp16(d + AOFF_L, g_bl + off);
    }
    #pragma unroll
    for (int p = 0; p < 2; p++) {
        const int idx = p * 256 + tid;
        const int r = idx >> 3, seg = idx & 7;
        const uint32_t d = bs + BOFF + SWZ(r * 128 + seg * 16);
        const size_t off = brow + (size_t)r * NN + c * 64 + seg * 8;
        cp16(d, g_hTh + off);
        cp16(d + (BOFF_L - BOFF), g_hTl + off);
    }
    asm volatile("cp.async.commit_group;" ::: "memory");
}

__global__ __launch_bounds__(256) void k_gemm(float* __restrict__ out) {
    extern __shared__ __align__(1024) char smem[];
    const uint32_t sb = smem_u32(smem);
    const int tid = threadIdx.x, lane = tid & 31, wid = tid >> 5;
    const int wm = wid >> 1, wn = wid & 1;
    const int g = blockIdx.y, i0 = blockIdx.x * 128;

    const size_t arow = (size_t)(g * NN + i0) * NN;
    const size_t brow = (size_t)g * FF * NN;

    float acc[2][4][4];
    #pragma unroll
    for (int mt = 0; mt < 2; mt++)
        #pragma unroll
        for (int nt = 0; nt < 4; nt++)
            #pragma unroll
            for (int q = 0; q < 4; q++) acc[mt][nt][q] = 0.f;

    const int arow_l = wm * 32 + (lane & 15);
    const int brow_l = wn * 32 + (lane & 7) + ((lane >> 4) & 1) * 8;
    const uint32_t akh = (lane >> 4) * 16;
    const uint32_t bkh = ((lane >> 3) & 1) * 16;

    // prologue: chunks 0 and 1
    load_chunk(sb, 0, arow, brow, tid);
    load_chunk(sb + BUFS, 1, arow, brow, tid);
    asm volatile("cp.async.wait_group 1;" ::: "memory");
    __syncthreads();

    for (int c = 0; c < 16; c++) {
        const uint32_t bs = sb + (c & 1) * BUFS;
        #pragma unroll
        for (int ks = 0; ks < 4; ks++) {
            const uint32_t kb = ks * 32;
            uint32_t ah[2][4], al[2][4];
            #pragma unroll
            for (int mt = 0; mt < 2; mt++) {
                const unsigned r = (unsigned)(arow_l + mt * 16);
                const uint32_t addr = bs + r * 128 + ((kb + akh) ^ ((r & 7) << 4));
                ldm4(ah[mt], addr);
                ldm4(al[mt], addr + AOFF_L);
            }
            uint32_t bh[2][4], bl[2][4];
            #pragma unroll
            for (int nt2 = 0; nt2 < 2; nt2++) {
                const unsigned r = (unsigned)(brow_l + nt2 * 16);
                const uint32_t addr = bs + BOFF + r * 128 + ((kb + bkh) ^ ((r & 7) << 4));
                ldm4(bh[nt2], addr);
                ldm4(bl[nt2], addr + (BOFF_L - BOFF));
            }
            #pragma unroll
            for (int mt = 0; mt < 2; mt++)
                #pragma unroll
                for (int nt = 0; nt < 4; nt++) {
                    const int nt2 = nt >> 1, s = (nt & 1) * 2;
                    mma16816(acc[mt][nt], ah[mt], bh[nt2][s], bh[nt2][s + 1]);
                    mma16816(acc[mt][nt], ah[mt], bl[nt2][s], bl[nt2][s + 1]);
                    mma16816(acc[mt][nt], al[mt], bh[nt2][s], bh[nt2][s + 1]);
                }
        }
        __syncthreads();
        if (c + 2 < 16) {
            load_chunk(bs, c + 2, arow, brow, tid);
            asm volatile("cp.async.wait_group 1;" ::: "memory");
        } else {
            asm volatile("cp.async.wait_group 0;" ::: "memory");
        }
        __syncthreads();
    }

    // epilogue: ELU + store
    const int g4 = lane >> 2, tig = lane & 3;
    #pragma unroll
    for (int mt = 0; mt < 2; mt++)
        #pragma unroll
        for (int nt = 0; nt < 4; nt++) {
            const int col = wn * 32 + nt * 8 + tig * 2;
            const int r0 = i0 + wm * 32 + mt * 16 + g4;
            float2 v0, v1;
            v0.x = acc[mt][nt][0]; v0.y = acc[mt][nt][1];
            v1.x = acc[mt][nt][2]; v1.y = acc[mt][nt][3];
            v0.x = (v0.x > 0.f) ? v0.x : (expf(v0.x) - 1.f);
            v0.y = (v0.y > 0.f) ? v0.y : (expf(v0.y) - 1.f);
            v1.x = (v1.x > 0.f) ? v1.x : (expf(v1.x) - 1.f);
            v1.y = (v1.y > 0.f) ? v1.y : (expf(v1.y) - 1.f);
            *(float2*)(out + ((size_t)(g * NN + r0)) * FF + col) = v0;
            *(float2*)(out + ((size_t)(g * NN + r0 + 8)) * FF + col) = v1;
        }
}

// ---------------- launcher ----------------
extern "C" void kernel_launch(void* const* d_in, const int* in_sizes, int n_in,
                              void* d_out, int out_size) {
    const float* atoms = (const float*)d_in[0];
    const int*   edges = (const int*)d_in[1];
    const float* W     = (const float*)d_in[2];
    const float* a     = (const float*)d_in[3];
    float* out = (float*)d_out;
    (void)in_sizes; (void)n_in; (void)out_size;

    cudaFuncSetAttribute(k_gemm, cudaFuncAttributeMaxDynamicSharedMemorySize, GEMM_SMEM);
    k_h<<<dim3(16, GB), 256>>>(atoms, W, a);
    k_uniq<<<(GB * NN) / 256, 256>>>(edges);
    k_blend<<<dim3(32, GB), 256>>>();
    k_gemm<<<dim3(8, GB), 256, GEMM_SMEM>>>(out);
}